// round 15
// baseline (speedup 1.0000x reference)
#include <cuda_runtime.h>
#include <cuda.h>
#include <cuda_fp16.h>
#include <math.h>
#include <stdint.h>

// ---------------- problem constants ----------------
#define Bv     64
#define Hd     28
#define Wd     28
#define Cc     512
#define NHEADS 16
#define WIN    7
#define SHIFTV 3
#define NTOK   49
#define NWIN   16
#define BWIN   (Bv*NWIN)
#define MROWS  (BWIN*NTOK)   // 50176
#define MLPH   2048
#define STAGES 3

// ---------------- scratch (allocation-free: device globals) ----------------
__device__ __half g_win[(size_t)MROWS * Cc];
__device__ __half g_qkv[(size_t)MROWS * 3 * Cc];
__device__ __half g_att[(size_t)MROWS * Cc];
__device__ __half g_x2 [(size_t)MROWS * Cc];          // fp16 residual
__device__ __half g_ln2[(size_t)MROWS * Cc];
__device__ __half g_hid[(size_t)MROWS * MLPH];
__device__ __half g_wqkvT[(size_t)(3*Cc) * Cc];
__device__ __half g_wprojT[(size_t)Cc * Cc];
__device__ __half g_wfc1T[(size_t)MLPH * Cc];
__device__ __half g_wfc2T[(size_t)Cc * MLPH];
__device__ __half g_bm[(size_t)16 * 16 * 64 * 64];    // fp16 bias+mask table

// ---------------- helpers ----------------
__device__ __forceinline__ uint32_t smem_u32(const void* p) {
    uint32_t a;
    asm("{ .reg .u64 t; cvta.to.shared.u64 t, %1; cvt.u32.u64 %0, t; }" : "=r"(a) : "l"(p));
    return a;
}
__device__ __forceinline__ void ldsm4(uint32_t* r, uint32_t addr) {
    asm volatile("ldmatrix.sync.aligned.m8n8.x4.b16 {%0,%1,%2,%3}, [%4];"
                 : "=r"(r[0]), "=r"(r[1]), "=r"(r[2]), "=r"(r[3]) : "r"(addr));
}
__device__ __forceinline__ void mma_f16(float* c, const uint32_t* a, const uint32_t* b) {
    asm volatile("mma.sync.aligned.m16n8k16.row.col.f32.f16.f16.f32 "
                 "{%0,%1,%2,%3}, {%4,%5,%6,%7}, {%8,%9}, {%0,%1,%2,%3};"
                 : "+f"(c[0]), "+f"(c[1]), "+f"(c[2]), "+f"(c[3])
                 : "r"(a[0]), "r"(a[1]), "r"(a[2]), "r"(a[3]), "r"(b[0]), "r"(b[1]));
}
__device__ __forceinline__ float gelu_fast(float x) {
    float u = 0.7978845608f * (x + 0.044715f * x * x * x);
    float t;
    asm("tanh.approx.f32 %0, %1;" : "=f"(t) : "f"(u));
    return 0.5f * x * (1.0f + t);
}

// ---------------- row map ----------------
__device__ __forceinline__ int map_row(int m) {
    int w = m / NTOK, n = m - w * NTOK;
    int b  = w >> 4, wi = w & 15;
    int wh = wi >> 2, ww = wi & 3;
    int r  = n / 7,  c  = n - r * 7;
    int oh = wh * 7 + r + SHIFTV; if (oh >= Hd) oh -= Hd;
    int ow = ww * 7 + c + SHIFTV; if (ow >= Wd) ow -= Wd;
    return b * (Hd * Wd) + oh * Wd + ow;
}

// ---------------- LayerNorm: TIN in -> fp16 out; 2 rows per 256-thread block ----------------
template<bool GATHER, typename TIN>
__global__ __launch_bounds__(256) void ln_kernel(const TIN* __restrict__ x,
                                                 const float* __restrict__ sc,
                                                 const float* __restrict__ bi,
                                                 __half* __restrict__ out)
{
    int half = threadIdx.x >> 7;
    int row = blockIdx.x * 2 + half;
    int src = GATHER ? map_row(row) : row;
    int t = threadIdx.x & 127;
    float4 v;
    if (sizeof(TIN) == 4) {
        v = ((const float4*)((const float*)x + (size_t)src * Cc))[t];
    } else {
        uint2 pk = ((const uint2*)((const __half*)x + (size_t)src * Cc))[t];
        float2 a = __half22float2(*(__half2*)&pk.x);
        float2 b = __half22float2(*(__half2*)&pk.y);
        v = make_float4(a.x, a.y, b.x, b.y);
    }
    float s = v.x + v.y + v.z + v.w;
    float q = v.x*v.x + v.y*v.y + v.z*v.z + v.w*v.w;
    #pragma unroll
    for (int o = 16; o; o >>= 1) {
        s += __shfl_xor_sync(0xffffffffu, s, o);
        q += __shfl_xor_sync(0xffffffffu, q, o);
    }
    __shared__ float ss[8], qq[8], stat[2][2];
    int wid = threadIdx.x >> 5;
    if ((threadIdx.x & 31) == 0) { ss[wid] = s; qq[wid] = q; }
    __syncthreads();
    if ((threadIdx.x & 127) == 0) {
        int b0 = half * 4;
        float S = ss[b0] + ss[b0+1] + ss[b0+2] + ss[b0+3];
        float Q = qq[b0] + qq[b0+1] + qq[b0+2] + qq[b0+3];
        float mean = S * (1.0f / Cc);
        float var  = Q * (1.0f / Cc) - mean * mean;
        stat[half][0] = mean; stat[half][1] = rsqrtf(var + 1e-5f);
    }
    __syncthreads();
    float mean = stat[half][0], rstd = stat[half][1];
    float4 sv = ((const float4*)sc)[t];
    float4 bv = ((const float4*)bi)[t];
    __half2 h0 = __floats2half2_rn((v.x - mean) * rstd * sv.x + bv.x,
                                   (v.y - mean) * rstd * sv.y + bv.y);
    __half2 h1 = __floats2half2_rn((v.z - mean) * rstd * sv.z + bv.z,
                                   (v.w - mean) * rstd * sv.w + bv.w);
    uint2 pk = make_uint2(*(uint32_t*)&h0, *(uint32_t*)&h1);
    ((uint2*)(out + (size_t)row * Cc))[t] = pk;
}

// ---------------- fused preamble: 4 weight transposes + fp16 bias/mask table ----------------
__device__ __forceinline__ void do_transpose(const float* in, __half* out, int K, int N,
                                             int bx, int by)
{
    __shared__ float t[32][33];
    int k0 = by * 32, n0 = bx * 32;
    int tx = threadIdx.x & 31, ty = threadIdx.x >> 5;
    #pragma unroll
    for (int i = ty; i < 32; i += 8) t[i][tx] = in[(size_t)(k0 + i) * N + n0 + tx];
    __syncthreads();
    #pragma unroll
    for (int i = ty; i < 32; i += 8)
        out[(size_t)(n0 + i) * K + k0 + tx] = __float2half(t[tx][i]);
}

__global__ __launch_bounds__(256) void preamble_kernel(
    const float* __restrict__ qkv_w, const float* __restrict__ proj_w,
    const float* __restrict__ fc1_w, const float* __restrict__ fc2_w,
    const float* __restrict__ rpbt,
    __half* __restrict__ wqkvT, __half* __restrict__ wprojT,
    __half* __restrict__ wfc1T, __half* __restrict__ wfc2T,
    __half* __restrict__ bmG)
{
    int b = blockIdx.x;
    if (b < 768) {
        do_transpose(qkv_w, wqkvT, Cc, 3*Cc, b % 48, b / 48);
    } else if (b < 1024) {
        int bb = b - 768;
        do_transpose(proj_w, wprojT, Cc, Cc, bb % 16, bb / 16);
    } else if (b < 2048) {
        int bb = b - 1024;
        do_transpose(fc1_w, wfc1T, Cc, MLPH, bb % 64, bb / 64);
    } else if (b < 3072) {
        int bb = b - 2048;
        do_transpose(fc2_w, wfc2T, MLPH, Cc, bb % 16, bb / 16);
    } else {
        int bb = b - 3072;
        int wi = bb >> 4, h = bb & 15;
        int wh = wi >> 2, ww = wi & 3;
        __half* bm = bmG + (size_t)bb * 4096;
        for (int p = threadIdx.x; p < 4096; p += 256) {
            int i = p >> 6, j = p & 63;
            float v;
            if (j >= NTOK) v = -60000.f;
            else if (i >= NTOK) v = 0.f;
            else {
                int ri = i / 7, ci = i - ri * 7;
                int rj = j / 7, cj = j - rj * 7;
                v = rpbt[((ri - rj + 6) * 13 + (ci - cj + 6)) * NHEADS + h];
                int hi = wh * 7 + ri, wwi = ww * 7 + ci;
                int hj = wh * 7 + rj, wwj = ww * 7 + cj;
                int ci_ = (hi >= 25 ? 2 : (hi >= 21 ? 1 : 0)) * 3 + (wwi >= 25 ? 2 : (wwi >= 21 ? 1 : 0));
                int cj_ = (hj >= 25 ? 2 : (hj >= 21 ? 1 : 0)) * 3 + (wwj >= 25 ? 2 : (wwj >= 21 ? 1 : 0));
                if (ci_ != cj_) v -= 100.f;
            }
            bm[p] = __float2half(v);
        }
    }
}

// ---------------- fp16 mma.sync GEMM: 128x128 CTA tile, 2 CTAs/SM (frozen r11 config) ----------------
enum { EPI_BIAS = 0, EPI_SCATTER = 1, EPI_GELU = 2, EPI_RESID = 3 };

template<int EPI, typename TOUT, typename TRES>
__global__ __launch_bounds__(256, 2) void gemm_tc(const __half* __restrict__ A,
                                                  const __half* __restrict__ Bt,
                                                  const float* __restrict__ bias,
                                                  const TRES* __restrict__ R,
                                                  TOUT* __restrict__ C,
                                                  int M, int N, int K)
{
    extern __shared__ char smem[];
    const uint32_t sb = smem_u32(smem);
    const int tid = threadIdx.x;
    const int wid = tid >> 5;
    const int lid = tid & 31;
    const int wm = wid & 3;
    const int wn = wid >> 2;

    const int row0 = blockIdx.y * 128;
    const int col0 = blockIdx.x * 128;
    const int NC = K >> 6;

    auto load_chunk = [&](int c) {
        const uint32_t st = sb + (uint32_t)(c % STAGES) * 32768u;
        const int k0 = c << 6;
        #pragma unroll
        for (int p = 0; p < 4; p++) {
            int l = p * 256 + tid; int r = l >> 3, u = l & 7;
            const __half* g = A + (size_t)(row0 + r) * K + k0 + u * 8;
            uint32_t off = (uint32_t)r * 128u + (uint32_t)((u ^ (r & 7)) << 4);
            asm volatile("cp.async.cg.shared.global [%0], [%1], 16;" :: "r"(st + off), "l"(g));
        }
        #pragma unroll
        for (int p = 0; p < 4; p++) {
            int l = p * 256 + tid; int r = l >> 3, u = l & 7;
            const __half* g = Bt + (size_t)(col0 + r) * K + k0 + u * 8;
            uint32_t off = 16384u + (uint32_t)r * 128u + (uint32_t)((u ^ (r & 7)) << 4);
            asm volatile("cp.async.cg.shared.global [%0], [%1], 16;" :: "r"(st + off), "l"(g));
        }
        asm volatile("cp.async.commit_group;" ::: "memory");
    };

    const uint32_t swz   = lid & 7;
    const uint32_t a_row = (lid & 7) + ((lid >> 3) & 1) * 8;
    const uint32_t a_khi = (lid >> 4);
    const uint32_t b_row = ((lid >> 4) & 1) * 8 + (lid & 7);
    const uint32_t b_khi = (lid >> 3) & 1;

    float acc[2][8][4];
    #pragma unroll
    for (int mt = 0; mt < 2; mt++)
        #pragma unroll
        for (int nt = 0; nt < 8; nt++)
            #pragma unroll
            for (int j = 0; j < 4; j++) acc[mt][nt][j] = 0.f;

    for (int c = 0; c < STAGES - 1; c++) load_chunk(c);

    for (int c = 0; c < NC; c++) {
        asm volatile("cp.async.wait_group %0;" :: "n"(STAGES - 2) : "memory");
        __syncthreads();

        if (c + STAGES - 1 < NC) load_chunk(c + STAGES - 1);
        else asm volatile("cp.async.commit_group;" ::: "memory");

        const uint32_t sA = sb + (uint32_t)(c % STAGES) * 32768u;
        const uint32_t sB = sA + 16384u;

        #pragma unroll
        for (int ks = 0; ks < 4; ks++) {
            uint32_t a[2][4];
            #pragma unroll
            for (int mt = 0; mt < 2; mt++) {
                uint32_t row = (uint32_t)(wm * 32 + mt * 16) + a_row;
                uint32_t kg  = (uint32_t)(ks * 2) + a_khi;
                ldsm4(a[mt], sA + row * 128u + ((kg ^ swz) << 4));
            }
            uint32_t b[8][2];
            #pragma unroll
            for (int i = 0; i < 4; i++) {
                uint32_t row = (uint32_t)(wn * 64 + i * 16) + b_row;
                uint32_t kg  = (uint32_t)(ks * 2) + b_khi;
                uint32_t r4[4];
                ldsm4(r4, sB + row * 128u + ((kg ^ swz) << 4));
                b[2*i][0]   = r4[0]; b[2*i][1]   = r4[1];
                b[2*i+1][0] = r4[2]; b[2*i+1][1] = r4[3];
            }
            #pragma unroll
            for (int mt = 0; mt < 2; mt++)
                #pragma unroll
                for (int nt = 0; nt < 8; nt++)
                    mma_f16(acc[mt][nt], a[mt], b[nt]);
        }
    }

    const int cbase = col0 + wn * 64 + (lid & 3) * 2;
    float2 bf[8];
    #pragma unroll
    for (int nt = 0; nt < 8; nt++) bf[nt] = *(const float2*)(bias + cbase + nt * 8);

    #pragma unroll
    for (int mt = 0; mt < 2; mt++) {
        #pragma unroll
        for (int h = 0; h < 2; h++) {
            int m = row0 + wm * 32 + mt * 16 + h * 8 + (lid >> 2);
            int drow = (EPI == EPI_SCATTER) ? map_row(m) : m;
            TOUT* cp = C + (size_t)drow * N + cbase;
            const TRES* rp = (EPI == EPI_SCATTER || EPI == EPI_RESID)
                             ? (R + (size_t)drow * N + cbase) : nullptr;
            #pragma unroll
            for (int nt = 0; nt < 8; nt++) {
                float vx = acc[mt][nt][h * 2 + 0] + bf[nt].x;
                float vy = acc[mt][nt][h * 2 + 1] + bf[nt].y;
                if (EPI == EPI_GELU) {
                    vx = gelu_fast(vx);
                    vy = gelu_fast(vy);
                }
                if (EPI == EPI_SCATTER || EPI == EPI_RESID) {
                    if (sizeof(TRES) == 2) {
                        __half2 rh = *(const __half2*)((const __half*)rp + nt * 8);
                        float2 rf = __half22float2(rh);
                        vx += rf.x; vy += rf.y;
                    } else {
                        float2 rv = *(const float2*)((const float*)rp + nt * 8);
                        vx += rv.x; vy += rv.y;
                    }
                }
                if (sizeof(TOUT) == 2) {
                    __half2 hv = __floats2half2_rn(vx, vy);
                    *(__half2*)((__half*)cp + nt * 8) = hv;
                } else {
                    *(float2*)((float*)cp + nt * 8) = make_float2(vx, vy);
                }
            }
        }
    }
}

// ---------------- windowed attention: 2 heads per CTA (256 thr, 8 warps) ----------------
// warps 0-3 -> head h0, warps 4-7 -> head h0+1; per-group smem identical to r14 layout.
__global__ __launch_bounds__(256) void attn_mma(const __half* __restrict__ qkv,
                                                const __half* __restrict__ bmG,
                                                __half* __restrict__ out)
{
    int w  = blockIdx.x >> 3;
    int h0 = (blockIdx.x & 7) * 2;
    __shared__ __half Qs[2][64][40];
    __shared__ __half Ks[2][64][40];
    __shared__ __half Vt[2][32][72];
    int tid = threadIdx.x, wrp = tid >> 5, lid = tid & 31;
    int grp = wrp >> 2, warp = wrp & 3;       // grp selects head; warp = role within group

    // cooperative load: both heads' 64-half rows are contiguous (128B per row per tensor)
    const __half* base = qkv + (size_t)w * NTOK * (3 * Cc) + h0 * 32;
    for (int p = tid; p < 64 * 32; p += 256) {
        int i = p >> 5, c = p & 31;           // c: 0..31 over 64 halfs (both heads)
        int hd = c >> 4, sg = (c & 15) * 2;   // head select, offset within head
        __half2 hq, hk, hv;
        if (i < NTOK) {
            const __half2* rp = (const __half2*)(base + (size_t)i * (3 * Cc) + hd * 32 + sg);
            hq = rp[0]; hk = rp[256]; hv = rp[512];
        } else {
            hq = __float2half2_rn(0.f); hk = hq; hv = hq;
        }
        *(__half2*)&Qs[hd][i][sg] = hq;
        *(__half2*)&Ks[hd][i][sg] = hk;
        Vt[hd][sg][i]     = __low2half(hv);
        Vt[hd][sg + 1][i] = __high2half(hv);
    }
    __syncthreads();

    uint32_t qb = smem_u32(&Qs[grp][0][0]);
    uint32_t kb = smem_u32(&Ks[grp][0][0]);
    uint32_t vb = smem_u32(&Vt[grp][0][0]);
    int g = lid >> 2, t = lid & 3;
    uint32_t arow = (lid & 7) + ((lid >> 3) & 1) * 8;
    uint32_t akhi = lid >> 4;
    uint32_t brow = ((lid >> 4) & 1) * 8 + (lid & 7);
    uint32_t bkhi = (lid >> 3) & 1;

    float acc[8][4];
    #pragma unroll
    for (int nt = 0; nt < 8; nt++)
        #pragma unroll
        for (int j = 0; j < 4; j++) acc[nt][j] = 0.f;

    #pragma unroll
    for (int kc = 0; kc < 2; kc++) {
        uint32_t a[4];
        ldsm4(a, qb + (uint32_t)(warp * 16 + arow) * 80u + (akhi * 8 + kc * 16) * 2u);
        #pragma unroll
        for (int jb = 0; jb < 4; jb++) {
            uint32_t r4[4];
            ldsm4(r4, kb + (uint32_t)(jb * 16 + brow) * 80u + (bkhi * 8 + kc * 16) * 2u);
            mma_f16(acc[2 * jb],     a, &r4[0]);
            mma_f16(acc[2 * jb + 1], a, &r4[2]);
        }
    }

    const __half* bmp = bmG + ((size_t)(w & 15) * 16 + (h0 + grp)) * 4096;
    int row0 = warp * 16 + g, row1 = row0 + 8;
    const float scale = 0.1767766953f;
    #pragma unroll
    for (int nt = 0; nt < 8; nt++) {
        int c = nt * 8 + t * 2;
        float2 b0 = __half22float2(*(const __half2*)(bmp + row0 * 64 + c));
        float2 b1 = __half22float2(*(const __half2*)(bmp + row1 * 64 + c));
        acc[nt][0] = acc[nt][0] * scale + b0.x;
        acc[nt][1] = acc[nt][1] * scale + b0.y;
        acc[nt][2] = acc[nt][2] * scale + b1.x;
        acc[nt][3] = acc[nt][3] * scale + b1.y;
    }

    float mx0 = -1e30f, mx1 = -1e30f;
    #pragma unroll
    for (int nt = 0; nt < 8; nt++) {
        mx0 = fmaxf(mx0, fmaxf(acc[nt][0], acc[nt][1]));
        mx1 = fmaxf(mx1, fmaxf(acc[nt][2], acc[nt][3]));
    }
    #pragma unroll
    for (int o = 1; o < 4; o <<= 1) {
        mx0 = fmaxf(mx0, __shfl_xor_sync(0xffffffffu, mx0, o));
        mx1 = fmaxf(mx1, __shfl_xor_sync(0xffffffffu, mx1, o));
    }
    float s0 = 0.f, s1 = 0.f;
    #pragma unroll
    for (int nt = 0; nt < 8; nt++) {
        acc[nt][0] = __expf(acc[nt][0] - mx0); s0 += acc[nt][0];
        acc[nt][1] = __expf(acc[nt][1] - mx0); s0 += acc[nt][1];
        acc[nt][2] = __expf(acc[nt][2] - mx1); s1 += acc[nt][2];
        acc[nt][3] = __expf(acc[nt][3] - mx1); s1 += acc[nt][3];
    }
    #pragma unroll
    for (int o = 1; o < 4; o <<= 1) {
        s0 += __shfl_xor_sync(0xffffffffu, s0, o);
        s1 += __shfl_xor_sync(0xffffffffu, s1, o);
    }
    float inv0 = 1.f / s0, inv1 = 1.f / s1;

    uint32_t pA[4][4];
    #pragma unroll
    for (int s = 0; s < 4; s++) {
        __half2 h0v = __floats2half2_rn(acc[2*s][0]   * inv0, acc[2*s][1]   * inv0);
        __half2 h1v = __floats2half2_rn(acc[2*s][2]   * inv1, acc[2*s][3]   * inv1);
        __half2 h2v = __floats2half2_rn(acc[2*s+1][0] * inv0, acc[2*s+1][1] * inv0);
        __half2 h3v = __floats2half2_rn(acc[2*s+1][2] * inv1, acc[2*s+1][3] * inv1);
        pA[s][0] = *(uint32_t*)&h0v; pA[s][1] = *(uint32_t*)&h1v;
        pA[s][2] = *(uint32_t*)&h2v; pA[s][3] = *(uint32_t*)&h3v;
    }

    float o_[4][4];
    #pragma unroll
    for (int dt = 0; dt < 4; dt++)
        #pragma unroll
        for (int j = 0; j < 4; j++) o_[dt][j] = 0.f;

    #pragma unroll
    for (int s = 0; s < 4; s++) {
        #pragma unroll
        for (int dn = 0; dn < 2; dn++) {
            uint32_t r4[4];
            ldsm4(r4, vb + (uint32_t)(dn * 16 + brow) * 144u + (bkhi * 8 + s * 16) * 2u);
            mma_f16(o_[2 * dn],     pA[s], &r4[0]);
            mma_f16(o_[2 * dn + 1], pA[s], &r4[2]);
        }
    }

    __half* ob = out + (size_t)w * NTOK * Cc + (h0 + grp) * 32;
    #pragma unroll
    for (int dt = 0; dt < 4; dt++) {
        int c = dt * 8 + t * 2;
        if (row0 < NTOK) {
            __half2 hv = __floats2half2_rn(o_[dt][0], o_[dt][1]);
            *(__half2*)(ob + (size_t)row0 * Cc + c) = hv;
        }
        if (row1 < NTOK) {
            __half2 hv = __floats2half2_rn(o_[dt][2], o_[dt][3]);
            *(__half2*)(ob + (size_t)row1 * Cc + c) = hv;
        }
    }
}

// ---------------- host launch ----------------
extern "C" void kernel_launch(void* const* d_in, const int* in_sizes, int n_in,
                              void* d_out, int out_size)
{
    const float* x      = (const float*)d_in[0];
    const float* qkv_w  = (const float*)d_in[1];
    const float* qkv_b  = (const float*)d_in[2];
    const float* proj_w = (const float*)d_in[3];
    const float* proj_b = (const float*)d_in[4];
    const float* rpbt   = (const float*)d_in[5];
    const float* n1_s   = (const float*)d_in[6];
    const float* n1_b   = (const float*)d_in[7];
    const float* n2_s   = (const float*)d_in[8];
    const float* n2_b   = (const float*)d_in[9];
    const float* fc1_w  = (const float*)d_in[10];
    const float* fc1_b  = (const float*)d_in[11];
    const float* fc2_w  = (const float*)d_in[12];
    const float* fc2_b  = (const float*)d_in[13];
    float* outp = (float*)d_out;

    __half *p_win, *p_qkv, *p_att, *p_x2, *p_ln2, *p_hid;
    __half *p_wqkvT, *p_wprojT, *p_wfc1T, *p_wfc2T, *p_bm;
    cudaGetSymbolAddress((void**)&p_win, g_win);
    cudaGetSymbolAddress((void**)&p_qkv, g_qkv);
    cudaGetSymbolAddress((void**)&p_att, g_att);
    cudaGetSymbolAddress((void**)&p_x2,  g_x2);
    cudaGetSymbolAddress((void**)&p_ln2, g_ln2);
    cudaGetSymbolAddress((void**)&p_hid, g_hid);
    cudaGetSymbolAddress((void**)&p_wqkvT, g_wqkvT);
    cudaGetSymbolAddress((void**)&p_wprojT, g_wprojT);
    cudaGetSymbolAddress((void**)&p_wfc1T, g_wfc1T);
    cudaGetSymbolAddress((void**)&p_wfc2T, g_wfc2T);
    cudaGetSymbolAddress((void**)&p_bm, g_bm);

    const int SMEM_BYTES = STAGES * 32768;   // 96 KB -> 2 CTAs/SM
    cudaFuncSetAttribute((const void*)gemm_tc<EPI_BIAS, __half, float>,    cudaFuncAttributeMaxDynamicSharedMemorySize, SMEM_BYTES);
    cudaFuncSetAttribute((const void*)gemm_tc<EPI_SCATTER, __half, float>, cudaFuncAttributeMaxDynamicSharedMemorySize, SMEM_BYTES);
    cudaFuncSetAttribute((const void*)gemm_tc<EPI_GELU, __half, float>,    cudaFuncAttributeMaxDynamicSharedMemorySize, SMEM_BYTES);
    cudaFuncSetAttribute((const void*)gemm_tc<EPI_RESID, float, __half>,   cudaFuncAttributeMaxDynamicSharedMemorySize, SMEM_BYTES);

    // 0) fused preamble: 4 weight transposes + fp16 bias/mask table (single launch)
    preamble_kernel<<<3328, 256>>>(qkv_w, proj_w, fc1_w, fc2_w, rpbt,
                                   p_wqkvT, p_wprojT, p_wfc1T, p_wfc2T, p_bm);

    // 1) LN1 + shift + window partition -> fp16 (2 rows/block)
    ln_kernel<true, float><<<MROWS/2, 256>>>(x, n1_s, n1_b, p_win);

    // 2) QKV GEMM -> fp16
    gemm_tc<EPI_BIAS, __half, float><<<dim3(3*Cc/128, MROWS/128), 256, SMEM_BYTES>>>(
        p_win, p_wqkvT, qkv_b, nullptr, p_qkv, MROWS, 3*Cc, Cc);

    // 3) windowed attention (tensor-core, 2 heads/CTA) -> fp16
    attn_mma<<<BWIN * NHEADS / 2, 256>>>(p_qkv, p_bm, p_att);

    // 4) proj GEMM + scatter + residual(x fp32) -> fp16 x2
    gemm_tc<EPI_SCATTER, __half, float><<<dim3(Cc/128, MROWS/128), 256, SMEM_BYTES>>>(
        p_att, p_wprojT, proj_b, x, p_x2, MROWS, Cc, Cc);

    // 5) LN2 (fp16 in) -> fp16 (2 rows/block)
    ln_kernel<false, __half><<<MROWS/2, 256>>>(p_x2, n2_s, n2_b, p_ln2);

    // 6) fc1 GEMM + fast GELU -> fp16
    gemm_tc<EPI_GELU, __half, float><<<dim3(MLPH/128, MROWS/128), 256, SMEM_BYTES>>>(
        p_ln2, p_wfc1T, fc1_b, nullptr, p_hid, MROWS, MLPH, Cc);

    // 7) fc2 GEMM + bias + residual(x2 fp16) -> fp32 out
    gemm_tc<EPI_RESID, float, __half><<<dim3(Cc/128, MROWS/128), 256, SMEM_BYTES>>>(
        p_hid, p_wfc2T, fc2_b, p_x2, outp, MROWS, Cc, MLPH);
}

// round 16
// speedup vs baseline: 1.0148x; 1.0148x over previous
#include <cuda_runtime.h>
#include <cuda.h>
#include <cuda_fp16.h>
#include <math.h>
#include <stdint.h>

// ---------------- problem constants ----------------
#define Bv     64
#define Hd     28
#define Wd     28
#define Cc     512
#define NHEADS 16
#define WIN    7
#define SHIFTV 3
#define NTOK   49
#define NWIN   16
#define BWIN   (Bv*NWIN)
#define MROWS  (BWIN*NTOK)   // 50176
#define MLPH   2048
#define STAGES 3

// ---------------- scratch (allocation-free: device globals) ----------------
__device__ __half g_win[(size_t)MROWS * Cc];
__device__ __half g_qkv[(size_t)MROWS * 3 * Cc];
__device__ __half g_att[(size_t)MROWS * Cc];
__device__ __half g_x2 [(size_t)MROWS * Cc];          // fp16 residual
__device__ __half g_ln2[(size_t)MROWS * Cc];
__device__ __half g_hid[(size_t)MROWS * MLPH];
__device__ __half g_wqkvT[(size_t)(3*Cc) * Cc];
__device__ __half g_wprojT[(size_t)Cc * Cc];
__device__ __half g_wfc1T[(size_t)MLPH * Cc];
__device__ __half g_wfc2T[(size_t)Cc * MLPH];
__device__ __half g_bm[(size_t)16 * 16 * 64 * 64];    // fp16 bias+mask table

// ---------------- helpers ----------------
__device__ __forceinline__ uint32_t smem_u32(const void* p) {
    uint32_t a;
    asm("{ .reg .u64 t; cvta.to.shared.u64 t, %1; cvt.u32.u64 %0, t; }" : "=r"(a) : "l"(p));
    return a;
}
__device__ __forceinline__ void ldsm4(uint32_t* r, uint32_t addr) {
    asm volatile("ldmatrix.sync.aligned.m8n8.x4.b16 {%0,%1,%2,%3}, [%4];"
                 : "=r"(r[0]), "=r"(r[1]), "=r"(r[2]), "=r"(r[3]) : "r"(addr));
}
__device__ __forceinline__ void mma_f16(float* c, const uint32_t* a, const uint32_t* b) {
    asm volatile("mma.sync.aligned.m16n8k16.row.col.f32.f16.f16.f32 "
                 "{%0,%1,%2,%3}, {%4,%5,%6,%7}, {%8,%9}, {%0,%1,%2,%3};"
                 : "+f"(c[0]), "+f"(c[1]), "+f"(c[2]), "+f"(c[3])
                 : "r"(a[0]), "r"(a[1]), "r"(a[2]), "r"(a[3]), "r"(b[0]), "r"(b[1]));
}
__device__ __forceinline__ float gelu_fast(float x) {
    float u = 0.7978845608f * (x + 0.044715f * x * x * x);
    float t;
    asm("tanh.approx.f32 %0, %1;" : "=f"(t) : "f"(u));
    return 0.5f * x * (1.0f + t);
}

// ---------------- row map ----------------
__device__ __forceinline__ int map_row(int m) {
    int w = m / NTOK, n = m - w * NTOK;
    int b  = w >> 4, wi = w & 15;
    int wh = wi >> 2, ww = wi & 3;
    int r  = n / 7,  c  = n - r * 7;
    int oh = wh * 7 + r + SHIFTV; if (oh >= Hd) oh -= Hd;
    int ow = ww * 7 + c + SHIFTV; if (ow >= Wd) ow -= Wd;
    return b * (Hd * Wd) + oh * Wd + ow;
}

// ---------------- LayerNorm: TIN in -> fp16 out; 2 rows per 256-thread block ----------------
template<bool GATHER, typename TIN>
__global__ __launch_bounds__(256) void ln_kernel(const TIN* __restrict__ x,
                                                 const float* __restrict__ sc,
                                                 const float* __restrict__ bi,
                                                 __half* __restrict__ out)
{
    int half = threadIdx.x >> 7;
    int row = blockIdx.x * 2 + half;
    int src = GATHER ? map_row(row) : row;
    int t = threadIdx.x & 127;
    float4 v;
    if (sizeof(TIN) == 4) {
        v = ((const float4*)((const float*)x + (size_t)src * Cc))[t];
    } else {
        uint2 pk = ((const uint2*)((const __half*)x + (size_t)src * Cc))[t];
        float2 a = __half22float2(*(__half2*)&pk.x);
        float2 b = __half22float2(*(__half2*)&pk.y);
        v = make_float4(a.x, a.y, b.x, b.y);
    }
    float s = v.x + v.y + v.z + v.w;
    float q = v.x*v.x + v.y*v.y + v.z*v.z + v.w*v.w;
    #pragma unroll
    for (int o = 16; o; o >>= 1) {
        s += __shfl_xor_sync(0xffffffffu, s, o);
        q += __shfl_xor_sync(0xffffffffu, q, o);
    }
    __shared__ float ss[8], qq[8], stat[2][2];
    int wid = threadIdx.x >> 5;
    if ((threadIdx.x & 31) == 0) { ss[wid] = s; qq[wid] = q; }
    __syncthreads();
    if ((threadIdx.x & 127) == 0) {
        int b0 = half * 4;
        float S = ss[b0] + ss[b0+1] + ss[b0+2] + ss[b0+3];
        float Q = qq[b0] + qq[b0+1] + qq[b0+2] + qq[b0+3];
        float mean = S * (1.0f / Cc);
        float var  = Q * (1.0f / Cc) - mean * mean;
        stat[half][0] = mean; stat[half][1] = rsqrtf(var + 1e-5f);
    }
    __syncthreads();
    float mean = stat[half][0], rstd = stat[half][1];
    float4 sv = ((const float4*)sc)[t];
    float4 bv = ((const float4*)bi)[t];
    __half2 h0 = __floats2half2_rn((v.x - mean) * rstd * sv.x + bv.x,
                                   (v.y - mean) * rstd * sv.y + bv.y);
    __half2 h1 = __floats2half2_rn((v.z - mean) * rstd * sv.z + bv.z,
                                   (v.w - mean) * rstd * sv.w + bv.w);
    uint2 pk = make_uint2(*(uint32_t*)&h0, *(uint32_t*)&h1);
    ((uint2*)(out + (size_t)row * Cc))[t] = pk;
}

// ---------------- fused preamble: 4 weight transposes + fp16 bias/mask table ----------------
__device__ __forceinline__ void do_transpose(const float* in, __half* out, int K, int N,
                                             int bx, int by)
{
    __shared__ float t[32][33];
    int k0 = by * 32, n0 = bx * 32;
    int tx = threadIdx.x & 31, ty = threadIdx.x >> 5;
    #pragma unroll
    for (int i = ty; i < 32; i += 8) t[i][tx] = in[(size_t)(k0 + i) * N + n0 + tx];
    __syncthreads();
    #pragma unroll
    for (int i = ty; i < 32; i += 8)
        out[(size_t)(n0 + i) * K + k0 + tx] = __float2half(t[tx][i]);
}

__global__ __launch_bounds__(256) void preamble_kernel(
    const float* __restrict__ qkv_w, const float* __restrict__ proj_w,
    const float* __restrict__ fc1_w, const float* __restrict__ fc2_w,
    const float* __restrict__ rpbt,
    __half* __restrict__ wqkvT, __half* __restrict__ wprojT,
    __half* __restrict__ wfc1T, __half* __restrict__ wfc2T,
    __half* __restrict__ bmG)
{
    int b = blockIdx.x;
    if (b < 768) {
        do_transpose(qkv_w, wqkvT, Cc, 3*Cc, b % 48, b / 48);
    } else if (b < 1024) {
        int bb = b - 768;
        do_transpose(proj_w, wprojT, Cc, Cc, bb % 16, bb / 16);
    } else if (b < 2048) {
        int bb = b - 1024;
        do_transpose(fc1_w, wfc1T, Cc, MLPH, bb % 64, bb / 64);
    } else if (b < 3072) {
        int bb = b - 2048;
        do_transpose(fc2_w, wfc2T, MLPH, Cc, bb % 16, bb / 16);
    } else {
        int bb = b - 3072;
        int wi = bb >> 4, h = bb & 15;
        int wh = wi >> 2, ww = wi & 3;
        __half* bm = bmG + (size_t)bb * 4096;
        for (int p = threadIdx.x; p < 4096; p += 256) {
            int i = p >> 6, j = p & 63;
            float v;
            if (j >= NTOK) v = -60000.f;
            else if (i >= NTOK) v = 0.f;
            else {
                int ri = i / 7, ci = i - ri * 7;
                int rj = j / 7, cj = j - rj * 7;
                v = rpbt[((ri - rj + 6) * 13 + (ci - cj + 6)) * NHEADS + h];
                int hi = wh * 7 + ri, wwi = ww * 7 + ci;
                int hj = wh * 7 + rj, wwj = ww * 7 + cj;
                int ci_ = (hi >= 25 ? 2 : (hi >= 21 ? 1 : 0)) * 3 + (wwi >= 25 ? 2 : (wwi >= 21 ? 1 : 0));
                int cj_ = (hj >= 25 ? 2 : (hj >= 21 ? 1 : 0)) * 3 + (wwj >= 25 ? 2 : (wwj >= 21 ? 1 : 0));
                if (ci_ != cj_) v -= 100.f;
            }
            bm[p] = __float2half(v);
        }
    }
}

// ---------------- fp16 mma.sync GEMM: 128x128 CTA tile, 2 CTAs/SM (frozen r11 config) ----------------
enum { EPI_BIAS = 0, EPI_SCATTER = 1, EPI_GELU = 2, EPI_RESID = 3 };

template<int EPI, typename TOUT, typename TRES>
__global__ __launch_bounds__(256, 2) void gemm_tc(const __half* __restrict__ A,
                                                  const __half* __restrict__ Bt,
                                                  const float* __restrict__ bias,
                                                  const TRES* __restrict__ R,
                                                  TOUT* __restrict__ C,
                                                  int M, int N, int K)
{
    extern __shared__ char smem[];
    const uint32_t sb = smem_u32(smem);
    const int tid = threadIdx.x;
    const int wid = tid >> 5;
    const int lid = tid & 31;
    const int wm = wid & 3;
    const int wn = wid >> 2;

    const int row0 = blockIdx.y * 128;
    const int col0 = blockIdx.x * 128;
    const int NC = K >> 6;

    auto load_chunk = [&](int c) {
        const uint32_t st = sb + (uint32_t)(c % STAGES) * 32768u;
        const int k0 = c << 6;
        #pragma unroll
        for (int p = 0; p < 4; p++) {
            int l = p * 256 + tid; int r = l >> 3, u = l & 7;
            const __half* g = A + (size_t)(row0 + r) * K + k0 + u * 8;
            uint32_t off = (uint32_t)r * 128u + (uint32_t)((u ^ (r & 7)) << 4);
            asm volatile("cp.async.cg.shared.global [%0], [%1], 16;" :: "r"(st + off), "l"(g));
        }
        #pragma unroll
        for (int p = 0; p < 4; p++) {
            int l = p * 256 + tid; int r = l >> 3, u = l & 7;
            const __half* g = Bt + (size_t)(col0 + r) * K + k0 + u * 8;
            uint32_t off = 16384u + (uint32_t)r * 128u + (uint32_t)((u ^ (r & 7)) << 4);
            asm volatile("cp.async.cg.shared.global [%0], [%1], 16;" :: "r"(st + off), "l"(g));
        }
        asm volatile("cp.async.commit_group;" ::: "memory");
    };

    const uint32_t swz   = lid & 7;
    const uint32_t a_row = (lid & 7) + ((lid >> 3) & 1) * 8;
    const uint32_t a_khi = (lid >> 4);
    const uint32_t b_row = ((lid >> 4) & 1) * 8 + (lid & 7);
    const uint32_t b_khi = (lid >> 3) & 1;

    float acc[2][8][4];
    #pragma unroll
    for (int mt = 0; mt < 2; mt++)
        #pragma unroll
        for (int nt = 0; nt < 8; nt++)
            #pragma unroll
            for (int j = 0; j < 4; j++) acc[mt][nt][j] = 0.f;

    for (int c = 0; c < STAGES - 1; c++) load_chunk(c);

    for (int c = 0; c < NC; c++) {
        asm volatile("cp.async.wait_group %0;" :: "n"(STAGES - 2) : "memory");
        __syncthreads();

        if (c + STAGES - 1 < NC) load_chunk(c + STAGES - 1);
        else asm volatile("cp.async.commit_group;" ::: "memory");

        const uint32_t sA = sb + (uint32_t)(c % STAGES) * 32768u;
        const uint32_t sB = sA + 16384u;

        #pragma unroll
        for (int ks = 0; ks < 4; ks++) {
            uint32_t a[2][4];
            #pragma unroll
            for (int mt = 0; mt < 2; mt++) {
                uint32_t row = (uint32_t)(wm * 32 + mt * 16) + a_row;
                uint32_t kg  = (uint32_t)(ks * 2) + a_khi;
                ldsm4(a[mt], sA + row * 128u + ((kg ^ swz) << 4));
            }
            uint32_t b[8][2];
            #pragma unroll
            for (int i = 0; i < 4; i++) {
                uint32_t row = (uint32_t)(wn * 64 + i * 16) + b_row;
                uint32_t kg  = (uint32_t)(ks * 2) + b_khi;
                uint32_t r4[4];
                ldsm4(r4, sB + row * 128u + ((kg ^ swz) << 4));
                b[2*i][0]   = r4[0]; b[2*i][1]   = r4[1];
                b[2*i+1][0] = r4[2]; b[2*i+1][1] = r4[3];
            }
            #pragma unroll
            for (int mt = 0; mt < 2; mt++)
                #pragma unroll
                for (int nt = 0; nt < 8; nt++)
                    mma_f16(acc[mt][nt], a[mt], b[nt]);
        }
    }

    const int cbase = col0 + wn * 64 + (lid & 3) * 2;
    float2 bf[8];
    #pragma unroll
    for (int nt = 0; nt < 8; nt++) bf[nt] = *(const float2*)(bias + cbase + nt * 8);

    #pragma unroll
    for (int mt = 0; mt < 2; mt++) {
        #pragma unroll
        for (int h = 0; h < 2; h++) {
            int m = row0 + wm * 32 + mt * 16 + h * 8 + (lid >> 2);
            int drow = (EPI == EPI_SCATTER) ? map_row(m) : m;
            TOUT* cp = C + (size_t)drow * N + cbase;
            const TRES* rp = (EPI == EPI_SCATTER || EPI == EPI_RESID)
                             ? (R + (size_t)drow * N + cbase) : nullptr;
            #pragma unroll
            for (int nt = 0; nt < 8; nt++) {
                float vx = acc[mt][nt][h * 2 + 0] + bf[nt].x;
                float vy = acc[mt][nt][h * 2 + 1] + bf[nt].y;
                if (EPI == EPI_GELU) {
                    vx = gelu_fast(vx);
                    vy = gelu_fast(vy);
                }
                if (EPI == EPI_SCATTER || EPI == EPI_RESID) {
                    if (sizeof(TRES) == 2) {
                        __half2 rh = *(const __half2*)((const __half*)rp + nt * 8);
                        float2 rf = __half22float2(rh);
                        vx += rf.x; vy += rf.y;
                    } else {
                        float2 rv = *(const float2*)((const float*)rp + nt * 8);
                        vx += rv.x; vy += rv.y;
                    }
                }
                if (sizeof(TOUT) == 2) {
                    __half2 hv = __floats2half2_rn(vx, vy);
                    *(__half2*)((__half*)cp + nt * 8) = hv;
                } else {
                    *(float2*)((float*)cp + nt * 8) = make_float2(vx, vy);
                }
            }
        }
    }
}

// ---------------- windowed attention via mma.sync (r14 body, occupancy-capped regs) ----------------
__global__ __launch_bounds__(128, 10) void attn_mma(const __half* __restrict__ qkv,
                                                    const __half* __restrict__ bmG,
                                                    __half* __restrict__ out)
{
    int w = blockIdx.x >> 4, h = blockIdx.x & 15;
    __shared__ __half Qs[64][40];
    __shared__ __half Ks[64][40];
    __shared__ __half Vt[32][72];
    int tid = threadIdx.x, warp = tid >> 5, lid = tid & 31;

    const __half* base = qkv + (size_t)w * NTOK * (3 * Cc) + h * 32;
    for (int p = tid; p < 64 * 16; p += 128) {
        int i = p >> 4, sg = (p & 15) * 2;
        __half2 hq, hk, hv;
        if (i < NTOK) {
            const __half2* rp = (const __half2*)(base + (size_t)i * (3 * Cc) + sg);
            hq = rp[0]; hk = rp[256]; hv = rp[512];
        } else {
            hq = __float2half2_rn(0.f); hk = hq; hv = hq;
        }
        *(__half2*)&Qs[i][sg] = hq;
        *(__half2*)&Ks[i][sg] = hk;
        Vt[sg][i]     = __low2half(hv);
        Vt[sg + 1][i] = __high2half(hv);
    }
    __syncthreads();

    uint32_t qb = smem_u32(&Qs[0][0]);
    uint32_t kb = smem_u32(&Ks[0][0]);
    uint32_t vb = smem_u32(&Vt[0][0]);
    int g = lid >> 2, t = lid & 3;
    uint32_t arow = (lid & 7) + ((lid >> 3) & 1) * 8;
    uint32_t akhi = lid >> 4;
    uint32_t brow = ((lid >> 4) & 1) * 8 + (lid & 7);
    uint32_t bkhi = (lid >> 3) & 1;

    float acc[8][4];
    #pragma unroll
    for (int nt = 0; nt < 8; nt++)
        #pragma unroll
        for (int j = 0; j < 4; j++) acc[nt][j] = 0.f;

    #pragma unroll
    for (int kc = 0; kc < 2; kc++) {
        uint32_t a[4];
        ldsm4(a, qb + (uint32_t)(warp * 16 + arow) * 80u + (akhi * 8 + kc * 16) * 2u);
        #pragma unroll
        for (int jb = 0; jb < 4; jb++) {
            uint32_t r4[4];
            ldsm4(r4, kb + (uint32_t)(jb * 16 + brow) * 80u + (bkhi * 8 + kc * 16) * 2u);
            mma_f16(acc[2 * jb],     a, &r4[0]);
            mma_f16(acc[2 * jb + 1], a, &r4[2]);
        }
    }

    const __half* bmp = bmG + ((size_t)(w & 15) * 16 + h) * 4096;
    int row0 = warp * 16 + g, row1 = row0 + 8;
    const float scale = 0.1767766953f;
    #pragma unroll
    for (int nt = 0; nt < 8; nt++) {
        int c = nt * 8 + t * 2;
        float2 b0 = __half22float2(*(const __half2*)(bmp + row0 * 64 + c));
        float2 b1 = __half22float2(*(const __half2*)(bmp + row1 * 64 + c));
        acc[nt][0] = acc[nt][0] * scale + b0.x;
        acc[nt][1] = acc[nt][1] * scale + b0.y;
        acc[nt][2] = acc[nt][2] * scale + b1.x;
        acc[nt][3] = acc[nt][3] * scale + b1.y;
    }

    float mx0 = -1e30f, mx1 = -1e30f;
    #pragma unroll
    for (int nt = 0; nt < 8; nt++) {
        mx0 = fmaxf(mx0, fmaxf(acc[nt][0], acc[nt][1]));
        mx1 = fmaxf(mx1, fmaxf(acc[nt][2], acc[nt][3]));
    }
    #pragma unroll
    for (int o = 1; o < 4; o <<= 1) {
        mx0 = fmaxf(mx0, __shfl_xor_sync(0xffffffffu, mx0, o));
        mx1 = fmaxf(mx1, __shfl_xor_sync(0xffffffffu, mx1, o));
    }
    float s0 = 0.f, s1 = 0.f;
    #pragma unroll
    for (int nt = 0; nt < 8; nt++) {
        acc[nt][0] = __expf(acc[nt][0] - mx0); s0 += acc[nt][0];
        acc[nt][1] = __expf(acc[nt][1] - mx0); s0 += acc[nt][1];
        acc[nt][2] = __expf(acc[nt][2] - mx1); s1 += acc[nt][2];
        acc[nt][3] = __expf(acc[nt][3] - mx1); s1 += acc[nt][3];
    }
    #pragma unroll
    for (int o = 1; o < 4; o <<= 1) {
        s0 += __shfl_xor_sync(0xffffffffu, s0, o);
        s1 += __shfl_xor_sync(0xffffffffu, s1, o);
    }
    float inv0 = 1.f / s0, inv1 = 1.f / s1;

    uint32_t pA[4][4];
    #pragma unroll
    for (int s = 0; s < 4; s++) {
        __half2 h0 = __floats2half2_rn(acc[2*s][0]   * inv0, acc[2*s][1]   * inv0);
        __half2 h1 = __floats2half2_rn(acc[2*s][2]   * inv1, acc[2*s][3]   * inv1);
        __half2 h2 = __floats2half2_rn(acc[2*s+1][0] * inv0, acc[2*s+1][1] * inv0);
        __half2 h3 = __floats2half2_rn(acc[2*s+1][2] * inv1, acc[2*s+1][3] * inv1);
        pA[s][0] = *(uint32_t*)&h0; pA[s][1] = *(uint32_t*)&h1;
        pA[s][2] = *(uint32_t*)&h2; pA[s][3] = *(uint32_t*)&h3;
    }

    float o_[4][4];
    #pragma unroll
    for (int dt = 0; dt < 4; dt++)
        #pragma unroll
        for (int j = 0; j < 4; j++) o_[dt][j] = 0.f;

    #pragma unroll
    for (int s = 0; s < 4; s++) {
        #pragma unroll
        for (int dn = 0; dn < 2; dn++) {
            uint32_t r4[4];
            ldsm4(r4, vb + (uint32_t)(dn * 16 + brow) * 144u + (bkhi * 8 + s * 16) * 2u);
            mma_f16(o_[2 * dn],     pA[s], &r4[0]);
            mma_f16(o_[2 * dn + 1], pA[s], &r4[2]);
        }
    }

    __half* ob = out + (size_t)w * NTOK * Cc + h * 32;
    #pragma unroll
    for (int dt = 0; dt < 4; dt++) {
        int c = dt * 8 + t * 2;
        if (row0 < NTOK) {
            __half2 hv = __floats2half2_rn(o_[dt][0], o_[dt][1]);
            *(__half2*)(ob + (size_t)row0 * Cc + c) = hv;
        }
        if (row1 < NTOK) {
            __half2 hv = __floats2half2_rn(o_[dt][2], o_[dt][3]);
            *(__half2*)(ob + (size_t)row1 * Cc + c) = hv;
        }
    }
}

// ---------------- host launch ----------------
extern "C" void kernel_launch(void* const* d_in, const int* in_sizes, int n_in,
                              void* d_out, int out_size)
{
    const float* x      = (const float*)d_in[0];
    const float* qkv_w  = (const float*)d_in[1];
    const float* qkv_b  = (const float*)d_in[2];
    const float* proj_w = (const float*)d_in[3];
    const float* proj_b = (const float*)d_in[4];
    const float* rpbt   = (const float*)d_in[5];
    const float* n1_s   = (const float*)d_in[6];
    const float* n1_b   = (const float*)d_in[7];
    const float* n2_s   = (const float*)d_in[8];
    const float* n2_b   = (const float*)d_in[9];
    const float* fc1_w  = (const float*)d_in[10];
    const float* fc1_b  = (const float*)d_in[11];
    const float* fc2_w  = (const float*)d_in[12];
    const float* fc2_b  = (const float*)d_in[13];
    float* outp = (float*)d_out;

    __half *p_win, *p_qkv, *p_att, *p_x2, *p_ln2, *p_hid;
    __half *p_wqkvT, *p_wprojT, *p_wfc1T, *p_wfc2T, *p_bm;
    cudaGetSymbolAddress((void**)&p_win, g_win);
    cudaGetSymbolAddress((void**)&p_qkv, g_qkv);
    cudaGetSymbolAddress((void**)&p_att, g_att);
    cudaGetSymbolAddress((void**)&p_x2,  g_x2);
    cudaGetSymbolAddress((void**)&p_ln2, g_ln2);
    cudaGetSymbolAddress((void**)&p_hid, g_hid);
    cudaGetSymbolAddress((void**)&p_wqkvT, g_wqkvT);
    cudaGetSymbolAddress((void**)&p_wprojT, g_wprojT);
    cudaGetSymbolAddress((void**)&p_wfc1T, g_wfc1T);
    cudaGetSymbolAddress((void**)&p_wfc2T, g_wfc2T);
    cudaGetSymbolAddress((void**)&p_bm, g_bm);

    const int SMEM_BYTES = STAGES * 32768;   // 96 KB -> 2 CTAs/SM
    cudaFuncSetAttribute((const void*)gemm_tc<EPI_BIAS, __half, float>,    cudaFuncAttributeMaxDynamicSharedMemorySize, SMEM_BYTES);
    cudaFuncSetAttribute((const void*)gemm_tc<EPI_SCATTER, __half, float>, cudaFuncAttributeMaxDynamicSharedMemorySize, SMEM_BYTES);
    cudaFuncSetAttribute((const void*)gemm_tc<EPI_GELU, __half, float>,    cudaFuncAttributeMaxDynamicSharedMemorySize, SMEM_BYTES);
    cudaFuncSetAttribute((const void*)gemm_tc<EPI_RESID, float, __half>,   cudaFuncAttributeMaxDynamicSharedMemorySize, SMEM_BYTES);

    // 0) fused preamble: 4 weight transposes + fp16 bias/mask table (single launch)
    preamble_kernel<<<3328, 256>>>(qkv_w, proj_w, fc1_w, fc2_w, rpbt,
                                   p_wqkvT, p_wprojT, p_wfc1T, p_wfc2T, p_bm);

    // 1) LN1 + shift + window partition -> fp16 (2 rows/block)
    ln_kernel<true, float><<<MROWS/2, 256>>>(x, n1_s, n1_b, p_win);

    // 2) QKV GEMM -> fp16
    gemm_tc<EPI_BIAS, __half, float><<<dim3(3*Cc/128, MROWS/128), 256, SMEM_BYTES>>>(
        p_win, p_wqkvT, qkv_b, nullptr, p_qkv, MROWS, 3*Cc, Cc);

    // 3) windowed attention (tensor-core, 1 head/CTA) -> fp16
    attn_mma<<<BWIN * NHEADS, 128>>>(p_qkv, p_bm, p_att);

    // 4) proj GEMM + scatter + residual(x fp32) -> fp16 x2
    gemm_tc<EPI_SCATTER, __half, float><<<dim3(Cc/128, MROWS/128), 256, SMEM_BYTES>>>(
        p_att, p_wprojT, proj_b, x, p_x2, MROWS, Cc, Cc);

    // 5) LN2 (fp16 in) -> fp16 (2 rows/block)
    ln_kernel<false, __half><<<MROWS/2, 256>>>(p_x2, n2_s, n2_b, p_ln2);

    // 6) fc1 GEMM + fast GELU -> fp16
    gemm_tc<EPI_GELU, __half, float><<<dim3(MLPH/128, MROWS/128), 256, SMEM_BYTES>>>(
        p_ln2, p_wfc1T, fc1_b, nullptr, p_hid, MROWS, MLPH, Cc);

    // 7) fc2 GEMM + bias + residual(x2 fp16) -> fp32 out
    gemm_tc<EPI_RESID, float, __half><<<dim3(Cc/128, MROWS/128), 256, SMEM_BYTES>>>(
        p_hid, p_wfc2T, fc2_b, p_x2, outp, MROWS, Cc, MLPH);
}

// round 17
// speedup vs baseline: 1.0161x; 1.0013x over previous
#include <cuda_runtime.h>
#include <cuda.h>
#include <cuda_fp16.h>
#include <math.h>
#include <stdint.h>

// ---------------- problem constants ----------------
#define Bv     64
#define Hd     28
#define Wd     28
#define Cc     512
#define NHEADS 16
#define WIN    7
#define SHIFTV 3
#define NTOK   49
#define NWIN   16
#define BWIN   (Bv*NWIN)
#define MROWS  (BWIN*NTOK)   // 50176
#define MLPH   2048
#define STAGES 3

// ---------------- scratch (allocation-free: device globals) ----------------
__device__ __half g_win[(size_t)MROWS * Cc];
__device__ __half g_qkv[(size_t)MROWS * 3 * Cc];
__device__ __half g_att[(size_t)MROWS * Cc];
__device__ __half g_x2 [(size_t)MROWS * Cc];          // fp16 residual
__device__ __half g_ln2[(size_t)MROWS * Cc];
__device__ __half g_hid[(size_t)MROWS * MLPH];
__device__ __half g_wqkvT[(size_t)(3*Cc) * Cc];
__device__ __half g_wprojT[(size_t)Cc * Cc];
__device__ __half g_wfc1T[(size_t)MLPH * Cc];
__device__ __half g_wfc2T[(size_t)Cc * MLPH];
__device__ __half g_bm[(size_t)16 * 16 * 64 * 64];    // fp16 bias+mask table

// ---------------- helpers ----------------
__device__ __forceinline__ uint32_t smem_u32(const void* p) {
    uint32_t a;
    asm("{ .reg .u64 t; cvta.to.shared.u64 t, %1; cvt.u32.u64 %0, t; }" : "=r"(a) : "l"(p));
    return a;
}
__device__ __forceinline__ void ldsm4(uint32_t* r, uint32_t addr) {
    asm volatile("ldmatrix.sync.aligned.m8n8.x4.b16 {%0,%1,%2,%3}, [%4];"
                 : "=r"(r[0]), "=r"(r[1]), "=r"(r[2]), "=r"(r[3]) : "r"(addr));
}
__device__ __forceinline__ void mma_f16(float* c, const uint32_t* a, const uint32_t* b) {
    asm volatile("mma.sync.aligned.m16n8k16.row.col.f32.f16.f16.f32 "
                 "{%0,%1,%2,%3}, {%4,%5,%6,%7}, {%8,%9}, {%0,%1,%2,%3};"
                 : "+f"(c[0]), "+f"(c[1]), "+f"(c[2]), "+f"(c[3])
                 : "r"(a[0]), "r"(a[1]), "r"(a[2]), "r"(a[3]), "r"(b[0]), "r"(b[1]));
}
__device__ __forceinline__ float gelu_fast(float x) {
    float u = 0.7978845608f * (x + 0.044715f * x * x * x);
    float t;
    asm("tanh.approx.f32 %0, %1;" : "=f"(t) : "f"(u));
    return 0.5f * x * (1.0f + t);
}

// ---------------- row map ----------------
__device__ __forceinline__ int map_row(int m) {
    int w = m / NTOK, n = m - w * NTOK;
    int b  = w >> 4, wi = w & 15;
    int wh = wi >> 2, ww = wi & 3;
    int r  = n / 7,  c  = n - r * 7;
    int oh = wh * 7 + r + SHIFTV; if (oh >= Hd) oh -= Hd;
    int ow = ww * 7 + c + SHIFTV; if (ow >= Wd) ow -= Wd;
    return b * (Hd * Wd) + oh * Wd + ow;
}

// ---------------- LayerNorm: TIN in -> fp16 out; 2 rows per 256-thread block ----------------
template<bool GATHER, typename TIN>
__global__ __launch_bounds__(256) void ln_kernel(const TIN* __restrict__ x,
                                                 const float* __restrict__ sc,
                                                 const float* __restrict__ bi,
                                                 __half* __restrict__ out)
{
    int half = threadIdx.x >> 7;
    int row = blockIdx.x * 2 + half;
    int src = GATHER ? map_row(row) : row;
    int t = threadIdx.x & 127;
    float4 v;
    if (sizeof(TIN) == 4) {
        v = ((const float4*)((const float*)x + (size_t)src * Cc))[t];
    } else {
        uint2 pk = ((const uint2*)((const __half*)x + (size_t)src * Cc))[t];
        float2 a = __half22float2(*(__half2*)&pk.x);
        float2 b = __half22float2(*(__half2*)&pk.y);
        v = make_float4(a.x, a.y, b.x, b.y);
    }
    float s = v.x + v.y + v.z + v.w;
    float q = v.x*v.x + v.y*v.y + v.z*v.z + v.w*v.w;
    #pragma unroll
    for (int o = 16; o; o >>= 1) {
        s += __shfl_xor_sync(0xffffffffu, s, o);
        q += __shfl_xor_sync(0xffffffffu, q, o);
    }
    __shared__ float ss[8], qq[8], stat[2][2];
    int wid = threadIdx.x >> 5;
    if ((threadIdx.x & 31) == 0) { ss[wid] = s; qq[wid] = q; }
    __syncthreads();
    if ((threadIdx.x & 127) == 0) {
        int b0 = half * 4;
        float S = ss[b0] + ss[b0+1] + ss[b0+2] + ss[b0+3];
        float Q = qq[b0] + qq[b0+1] + qq[b0+2] + qq[b0+3];
        float mean = S * (1.0f / Cc);
        float var  = Q * (1.0f / Cc) - mean * mean;
        stat[half][0] = mean; stat[half][1] = rsqrtf(var + 1e-5f);
    }
    __syncthreads();
    float mean = stat[half][0], rstd = stat[half][1];
    float4 sv = ((const float4*)sc)[t];
    float4 bv = ((const float4*)bi)[t];
    __half2 h0 = __floats2half2_rn((v.x - mean) * rstd * sv.x + bv.x,
                                   (v.y - mean) * rstd * sv.y + bv.y);
    __half2 h1 = __floats2half2_rn((v.z - mean) * rstd * sv.z + bv.z,
                                   (v.w - mean) * rstd * sv.w + bv.w);
    uint2 pk = make_uint2(*(uint32_t*)&h0, *(uint32_t*)&h1);
    ((uint2*)(out + (size_t)row * Cc))[t] = pk;
}

// ---------------- fused preamble: 4 weight transposes + fp16 bias/mask table ----------------
__device__ __forceinline__ void do_transpose(const float* in, __half* out, int K, int N,
                                             int bx, int by)
{
    __shared__ float t[32][33];
    int k0 = by * 32, n0 = bx * 32;
    int tx = threadIdx.x & 31, ty = threadIdx.x >> 5;
    #pragma unroll
    for (int i = ty; i < 32; i += 8) t[i][tx] = in[(size_t)(k0 + i) * N + n0 + tx];
    __syncthreads();
    #pragma unroll
    for (int i = ty; i < 32; i += 8)
        out[(size_t)(n0 + i) * K + k0 + tx] = __float2half(t[tx][i]);
}

__global__ __launch_bounds__(256) void preamble_kernel(
    const float* __restrict__ qkv_w, const float* __restrict__ proj_w,
    const float* __restrict__ fc1_w, const float* __restrict__ fc2_w,
    const float* __restrict__ rpbt,
    __half* __restrict__ wqkvT, __half* __restrict__ wprojT,
    __half* __restrict__ wfc1T, __half* __restrict__ wfc2T,
    __half* __restrict__ bmG)
{
    int b = blockIdx.x;
    if (b < 768) {
        do_transpose(qkv_w, wqkvT, Cc, 3*Cc, b % 48, b / 48);
    } else if (b < 1024) {
        int bb = b - 768;
        do_transpose(proj_w, wprojT, Cc, Cc, bb % 16, bb / 16);
    } else if (b < 2048) {
        int bb = b - 1024;
        do_transpose(fc1_w, wfc1T, Cc, MLPH, bb % 64, bb / 64);
    } else if (b < 3072) {
        int bb = b - 2048;
        do_transpose(fc2_w, wfc2T, MLPH, Cc, bb % 16, bb / 16);
    } else {
        int bb = b - 3072;
        int wi = bb >> 4, h = bb & 15;
        int wh = wi >> 2, ww = wi & 3;
        __half* bm = bmG + (size_t)bb * 4096;
        for (int p = threadIdx.x; p < 4096; p += 256) {
            int i = p >> 6, j = p & 63;
            float v;
            if (j >= NTOK) v = -60000.f;
            else if (i >= NTOK) v = 0.f;
            else {
                int ri = i / 7, ci = i - ri * 7;
                int rj = j / 7, cj = j - rj * 7;
                v = rpbt[((ri - rj + 6) * 13 + (ci - cj + 6)) * NHEADS + h];
                int hi = wh * 7 + ri, wwi = ww * 7 + ci;
                int hj = wh * 7 + rj, wwj = ww * 7 + cj;
                int ci_ = (hi >= 25 ? 2 : (hi >= 21 ? 1 : 0)) * 3 + (wwi >= 25 ? 2 : (wwi >= 21 ? 1 : 0));
                int cj_ = (hj >= 25 ? 2 : (hj >= 21 ? 1 : 0)) * 3 + (wwj >= 25 ? 2 : (wwj >= 21 ? 1 : 0));
                if (ci_ != cj_) v -= 100.f;
            }
            bm[p] = __float2half(v);
        }
    }
}

// ---------------- fp16 mma.sync GEMM: 128x128 CTA tile, 2 CTAs/SM (frozen r11 config) ----------------
enum { EPI_BIAS = 0, EPI_SCATTER = 1, EPI_GELU = 2, EPI_RESID = 3 };

template<int EPI, typename TOUT, typename TRES>
__global__ __launch_bounds__(256, 2) void gemm_tc(const __half* __restrict__ A,
                                                  const __half* __restrict__ Bt,
                                                  const float* __restrict__ bias,
                                                  const TRES* __restrict__ R,
                                                  TOUT* __restrict__ C,
                                                  int M, int N, int K)
{
    extern __shared__ char smem[];
    const uint32_t sb = smem_u32(smem);
    const int tid = threadIdx.x;
    const int wid = tid >> 5;
    const int lid = tid & 31;
    const int wm = wid & 3;
    const int wn = wid >> 2;

    const int row0 = blockIdx.y * 128;
    const int col0 = blockIdx.x * 128;
    const int NC = K >> 6;

    auto load_chunk = [&](int c) {
        const uint32_t st = sb + (uint32_t)(c % STAGES) * 32768u;
        const int k0 = c << 6;
        #pragma unroll
        for (int p = 0; p < 4; p++) {
            int l = p * 256 + tid; int r = l >> 3, u = l & 7;
            const __half* g = A + (size_t)(row0 + r) * K + k0 + u * 8;
            uint32_t off = (uint32_t)r * 128u + (uint32_t)((u ^ (r & 7)) << 4);
            asm volatile("cp.async.cg.shared.global [%0], [%1], 16;" :: "r"(st + off), "l"(g));
        }
        #pragma unroll
        for (int p = 0; p < 4; p++) {
            int l = p * 256 + tid; int r = l >> 3, u = l & 7;
            const __half* g = Bt + (size_t)(col0 + r) * K + k0 + u * 8;
            uint32_t off = 16384u + (uint32_t)r * 128u + (uint32_t)((u ^ (r & 7)) << 4);
            asm volatile("cp.async.cg.shared.global [%0], [%1], 16;" :: "r"(st + off), "l"(g));
        }
        asm volatile("cp.async.commit_group;" ::: "memory");
    };

    const uint32_t swz   = lid & 7;
    const uint32_t a_row = (lid & 7) + ((lid >> 3) & 1) * 8;
    const uint32_t a_khi = (lid >> 4);
    const uint32_t b_row = ((lid >> 4) & 1) * 8 + (lid & 7);
    const uint32_t b_khi = (lid >> 3) & 1;

    float acc[2][8][4];
    #pragma unroll
    for (int mt = 0; mt < 2; mt++)
        #pragma unroll
        for (int nt = 0; nt < 8; nt++)
            #pragma unroll
            for (int j = 0; j < 4; j++) acc[mt][nt][j] = 0.f;

    for (int c = 0; c < STAGES - 1; c++) load_chunk(c);

    for (int c = 0; c < NC; c++) {
        asm volatile("cp.async.wait_group %0;" :: "n"(STAGES - 2) : "memory");
        __syncthreads();

        if (c + STAGES - 1 < NC) load_chunk(c + STAGES - 1);
        else asm volatile("cp.async.commit_group;" ::: "memory");

        const uint32_t sA = sb + (uint32_t)(c % STAGES) * 32768u;
        const uint32_t sB = sA + 16384u;

        #pragma unroll
        for (int ks = 0; ks < 4; ks++) {
            uint32_t a[2][4];
            #pragma unroll
            for (int mt = 0; mt < 2; mt++) {
                uint32_t row = (uint32_t)(wm * 32 + mt * 16) + a_row;
                uint32_t kg  = (uint32_t)(ks * 2) + a_khi;
                ldsm4(a[mt], sA + row * 128u + ((kg ^ swz) << 4));
            }
            uint32_t b[8][2];
            #pragma unroll
            for (int i = 0; i < 4; i++) {
                uint32_t row = (uint32_t)(wn * 64 + i * 16) + b_row;
                uint32_t kg  = (uint32_t)(ks * 2) + b_khi;
                uint32_t r4[4];
                ldsm4(r4, sB + row * 128u + ((kg ^ swz) << 4));
                b[2*i][0]   = r4[0]; b[2*i][1]   = r4[1];
                b[2*i+1][0] = r4[2]; b[2*i+1][1] = r4[3];
            }
            #pragma unroll
            for (int mt = 0; mt < 2; mt++)
                #pragma unroll
                for (int nt = 0; nt < 8; nt++)
                    mma_f16(acc[mt][nt], a[mt], b[nt]);
        }
    }

    const int cbase = col0 + wn * 64 + (lid & 3) * 2;
    float2 bf[8];
    #pragma unroll
    for (int nt = 0; nt < 8; nt++) bf[nt] = *(const float2*)(bias + cbase + nt * 8);

    #pragma unroll
    for (int mt = 0; mt < 2; mt++) {
        #pragma unroll
        for (int h = 0; h < 2; h++) {
            int m = row0 + wm * 32 + mt * 16 + h * 8 + (lid >> 2);
            int drow = (EPI == EPI_SCATTER) ? map_row(m) : m;
            TOUT* cp = C + (size_t)drow * N + cbase;
            const TRES* rp = (EPI == EPI_SCATTER || EPI == EPI_RESID)
                             ? (R + (size_t)drow * N + cbase) : nullptr;
            #pragma unroll
            for (int nt = 0; nt < 8; nt++) {
                float vx = acc[mt][nt][h * 2 + 0] + bf[nt].x;
                float vy = acc[mt][nt][h * 2 + 1] + bf[nt].y;
                if (EPI == EPI_GELU) {
                    vx = gelu_fast(vx);
                    vy = gelu_fast(vy);
                }
                if (EPI == EPI_SCATTER || EPI == EPI_RESID) {
                    if (sizeof(TRES) == 2) {
                        __half2 rh = *(const __half2*)((const __half*)rp + nt * 8);
                        float2 rf = __half22float2(rh);
                        vx += rf.x; vy += rf.y;
                    } else {
                        float2 rv = *(const float2*)((const float*)rp + nt * 8);
                        vx += rv.x; vy += rv.y;
                    }
                }
                if (sizeof(TOUT) == 2) {
                    __half2 hv = __floats2half2_rn(vx, vy);
                    *(__half2*)((__half*)cp + nt * 8) = hv;
                } else {
                    *(float2*)((float*)cp + nt * 8) = make_float2(vx, vy);
                }
            }
        }
    }
}

// ---------------- windowed attention via mma.sync; bm staged in smem ----------------
// smem: Qs/Ks [64][40], Vt [32][72], Bs [64][72] (pitch 36 words -> conflict-free reads)
__global__ __launch_bounds__(128, 9) void attn_mma(const __half* __restrict__ qkv,
                                                   const __half* __restrict__ bmG,
                                                   __half* __restrict__ out)
{
    int w = blockIdx.x >> 4, h = blockIdx.x & 15;
    __shared__ __half Qs[64][40];
    __shared__ __half Ks[64][40];
    __shared__ __half Vt[32][72];
    __shared__ __half Bs[64][72];
    int tid = threadIdx.x, warp = tid >> 5, lid = tid & 31;

    // coalesced bm stage: 64 rows x 64 halfs (128B) in 16B chunks
    const __half* bmp0 = bmG + ((size_t)(w & 15) * 16 + h) * 4096;
    #pragma unroll
    for (int p = tid; p < 512; p += 128) {
        int r = p >> 3, s = p & 7;
        *(uint4*)&Bs[r][s * 8] = *(const uint4*)(bmp0 + r * 64 + s * 8);
    }

    const __half* base = qkv + (size_t)w * NTOK * (3 * Cc) + h * 32;
    for (int p = tid; p < 64 * 16; p += 128) {
        int i = p >> 4, sg = (p & 15) * 2;
        __half2 hq, hk, hv;
        if (i < NTOK) {
            const __half2* rp = (const __half2*)(base + (size_t)i * (3 * Cc) + sg);
            hq = rp[0]; hk = rp[256]; hv = rp[512];
        } else {
            hq = __float2half2_rn(0.f); hk = hq; hv = hq;
        }
        *(__half2*)&Qs[i][sg] = hq;
        *(__half2*)&Ks[i][sg] = hk;
        Vt[sg][i]     = __low2half(hv);
        Vt[sg + 1][i] = __high2half(hv);
    }
    __syncthreads();

    uint32_t qb = smem_u32(&Qs[0][0]);
    uint32_t kb = smem_u32(&Ks[0][0]);
    uint32_t vb = smem_u32(&Vt[0][0]);
    int g = lid >> 2, t = lid & 3;
    uint32_t arow = (lid & 7) + ((lid >> 3) & 1) * 8;
    uint32_t akhi = lid >> 4;
    uint32_t brow = ((lid >> 4) & 1) * 8 + (lid & 7);
    uint32_t bkhi = (lid >> 3) & 1;

    float acc[8][4];
    #pragma unroll
    for (int nt = 0; nt < 8; nt++)
        #pragma unroll
        for (int j = 0; j < 4; j++) acc[nt][j] = 0.f;

    #pragma unroll
    for (int kc = 0; kc < 2; kc++) {
        uint32_t a[4];
        ldsm4(a, qb + (uint32_t)(warp * 16 + arow) * 80u + (akhi * 8 + kc * 16) * 2u);
        #pragma unroll
        for (int jb = 0; jb < 4; jb++) {
            uint32_t r4[4];
            ldsm4(r4, kb + (uint32_t)(jb * 16 + brow) * 80u + (bkhi * 8 + kc * 16) * 2u);
            mma_f16(acc[2 * jb],     a, &r4[0]);
            mma_f16(acc[2 * jb + 1], a, &r4[2]);
        }
    }

    int row0 = warp * 16 + g, row1 = row0 + 8;
    const float scale = 0.1767766953f;
    #pragma unroll
    for (int nt = 0; nt < 8; nt++) {
        int c = nt * 8 + t * 2;
        float2 b0 = __half22float2(*(const __half2*)&Bs[row0][c]);
        float2 b1 = __half22float2(*(const __half2*)&Bs[row1][c]);
        acc[nt][0] = acc[nt][0] * scale + b0.x;
        acc[nt][1] = acc[nt][1] * scale + b0.y;
        acc[nt][2] = acc[nt][2] * scale + b1.x;
        acc[nt][3] = acc[nt][3] * scale + b1.y;
    }

    float mx0 = -1e30f, mx1 = -1e30f;
    #pragma unroll
    for (int nt = 0; nt < 8; nt++) {
        mx0 = fmaxf(mx0, fmaxf(acc[nt][0], acc[nt][1]));
        mx1 = fmaxf(mx1, fmaxf(acc[nt][2], acc[nt][3]));
    }
    #pragma unroll
    for (int o = 1; o < 4; o <<= 1) {
        mx0 = fmaxf(mx0, __shfl_xor_sync(0xffffffffu, mx0, o));
        mx1 = fmaxf(mx1, __shfl_xor_sync(0xffffffffu, mx1, o));
    }
    float s0 = 0.f, s1 = 0.f;
    #pragma unroll
    for (int nt = 0; nt < 8; nt++) {
        acc[nt][0] = __expf(acc[nt][0] - mx0); s0 += acc[nt][0];
        acc[nt][1] = __expf(acc[nt][1] - mx0); s0 += acc[nt][1];
        acc[nt][2] = __expf(acc[nt][2] - mx1); s1 += acc[nt][2];
        acc[nt][3] = __expf(acc[nt][3] - mx1); s1 += acc[nt][3];
    }
    #pragma unroll
    for (int o = 1; o < 4; o <<= 1) {
        s0 += __shfl_xor_sync(0xffffffffu, s0, o);
        s1 += __shfl_xor_sync(0xffffffffu, s1, o);
    }
    float inv0 = 1.f / s0, inv1 = 1.f / s1;

    uint32_t pA[4][4];
    #pragma unroll
    for (int s = 0; s < 4; s++) {
        __half2 h0 = __floats2half2_rn(acc[2*s][0]   * inv0, acc[2*s][1]   * inv0);
        __half2 h1 = __floats2half2_rn(acc[2*s][2]   * inv1, acc[2*s][3]   * inv1);
        __half2 h2 = __floats2half2_rn(acc[2*s+1][0] * inv0, acc[2*s+1][1] * inv0);
        __half2 h3 = __floats2half2_rn(acc[2*s+1][2] * inv1, acc[2*s+1][3] * inv1);
        pA[s][0] = *(uint32_t*)&h0; pA[s][1] = *(uint32_t*)&h1;
        pA[s][2] = *(uint32_t*)&h2; pA[s][3] = *(uint32_t*)&h3;
    }

    float o_[4][4];
    #pragma unroll
    for (int dt = 0; dt < 4; dt++)
        #pragma unroll
        for (int j = 0; j < 4; j++) o_[dt][j] = 0.f;

    #pragma unroll
    for (int s = 0; s < 4; s++) {
        #pragma unroll
        for (int dn = 0; dn < 2; dn++) {
            uint32_t r4[4];
            ldsm4(r4, vb + (uint32_t)(dn * 16 + brow) * 144u + (bkhi * 8 + s * 16) * 2u);
            mma_f16(o_[2 * dn],     pA[s], &r4[0]);
            mma_f16(o_[2 * dn + 1], pA[s], &r4[2]);
        }
    }

    __half* ob = out + (size_t)w * NTOK * Cc + h * 32;
    #pragma unroll
    for (int dt = 0; dt < 4; dt++) {
        int c = dt * 8 + t * 2;
        if (row0 < NTOK) {
            __half2 hv = __floats2half2_rn(o_[dt][0], o_[dt][1]);
            *(__half2*)(ob + (size_t)row0 * Cc + c) = hv;
        }
        if (row1 < NTOK) {
            __half2 hv = __floats2half2_rn(o_[dt][2], o_[dt][3]);
            *(__half2*)(ob + (size_t)row1 * Cc + c) = hv;
        }
    }
}

// ---------------- host launch ----------------
extern "C" void kernel_launch(void* const* d_in, const int* in_sizes, int n_in,
                              void* d_out, int out_size)
{
    const float* x      = (const float*)d_in[0];
    const float* qkv_w  = (const float*)d_in[1];
    const float* qkv_b  = (const float*)d_in[2];
    const float* proj_w = (const float*)d_in[3];
    const float* proj_b = (const float*)d_in[4];
    const float* rpbt   = (const float*)d_in[5];
    const float* n1_s   = (const float*)d_in[6];
    const float* n1_b   = (const float*)d_in[7];
    const float* n2_s   = (const float*)d_in[8];
    const float* n2_b   = (const float*)d_in[9];
    const float* fc1_w  = (const float*)d_in[10];
    const float* fc1_b  = (const float*)d_in[11];
    const float* fc2_w  = (const float*)d_in[12];
    const float* fc2_b  = (const float*)d_in[13];
    float* outp = (float*)d_out;

    __half *p_win, *p_qkv, *p_att, *p_x2, *p_ln2, *p_hid;
    __half *p_wqkvT, *p_wprojT, *p_wfc1T, *p_wfc2T, *p_bm;
    cudaGetSymbolAddress((void**)&p_win, g_win);
    cudaGetSymbolAddress((void**)&p_qkv, g_qkv);
    cudaGetSymbolAddress((void**)&p_att, g_att);
    cudaGetSymbolAddress((void**)&p_x2,  g_x2);
    cudaGetSymbolAddress((void**)&p_ln2, g_ln2);
    cudaGetSymbolAddress((void**)&p_hid, g_hid);
    cudaGetSymbolAddress((void**)&p_wqkvT, g_wqkvT);
    cudaGetSymbolAddress((void**)&p_wprojT, g_wprojT);
    cudaGetSymbolAddress((void**)&p_wfc1T, g_wfc1T);
    cudaGetSymbolAddress((void**)&p_wfc2T, g_wfc2T);
    cudaGetSymbolAddress((void**)&p_bm, g_bm);

    const int SMEM_BYTES = STAGES * 32768;   // 96 KB -> 2 CTAs/SM
    cudaFuncSetAttribute((const void*)gemm_tc<EPI_BIAS, __half, float>,    cudaFuncAttributeMaxDynamicSharedMemorySize, SMEM_BYTES);
    cudaFuncSetAttribute((const void*)gemm_tc<EPI_SCATTER, __half, float>, cudaFuncAttributeMaxDynamicSharedMemorySize, SMEM_BYTES);
    cudaFuncSetAttribute((const void*)gemm_tc<EPI_GELU, __half, float>,    cudaFuncAttributeMaxDynamicSharedMemorySize, SMEM_BYTES);
    cudaFuncSetAttribute((const void*)gemm_tc<EPI_RESID, float, __half>,   cudaFuncAttributeMaxDynamicSharedMemorySize, SMEM_BYTES);

    // 0) fused preamble: 4 weight transposes + fp16 bias/mask table (single launch)
    preamble_kernel<<<3328, 256>>>(qkv_w, proj_w, fc1_w, fc2_w, rpbt,
                                   p_wqkvT, p_wprojT, p_wfc1T, p_wfc2T, p_bm);

    // 1) LN1 + shift + window partition -> fp16 (2 rows/block)
    ln_kernel<true, float><<<MROWS/2, 256>>>(x, n1_s, n1_b, p_win);

    // 2) QKV GEMM -> fp16
    gemm_tc<EPI_BIAS, __half, float><<<dim3(3*Cc/128, MROWS/128), 256, SMEM_BYTES>>>(
        p_win, p_wqkvT, qkv_b, nullptr, p_qkv, MROWS, 3*Cc, Cc);

    // 3) windowed attention (tensor-core, smem-staged bm) -> fp16
    attn_mma<<<BWIN * NHEADS, 128>>>(p_qkv, p_bm, p_att);

    // 4) proj GEMM + scatter + residual(x fp32) -> fp16 x2
    gemm_tc<EPI_SCATTER, __half, float><<<dim3(Cc/128, MROWS/128), 256, SMEM_BYTES>>>(
        p_att, p_wprojT, proj_b, x, p_x2, MROWS, Cc, Cc);

    // 5) LN2 (fp16 in) -> fp16 (2 rows/block)
    ln_kernel<false, __half><<<MROWS/2, 256>>>(p_x2, n2_s, n2_b, p_ln2);

    // 6) fc1 GEMM + fast GELU -> fp16
    gemm_tc<EPI_GELU, __half, float><<<dim3(MLPH/128, MROWS/128), 256, SMEM_BYTES>>>(
        p_ln2, p_wfc1T, fc1_b, nullptr, p_hid, MROWS, MLPH, Cc);

    // 7) fc2 GEMM + bias + residual(x2 fp16) -> fp32 out
    gemm_tc<EPI_RESID, float, __half><<<dim3(Cc/128, MROWS/128), 256, SMEM_BYTES>>>(
        p_hid, p_wfc2T, fc2_b, p_x2, outp, MROWS, Cc, MLPH);
}